// round 5
// baseline (speedup 1.0000x reference)
#include <cuda_runtime.h>
#include <cstdint>

// OctonionLinear as dense tf32 mma.sync GEMM (portable sm_103 target — no tcgen05):
//   Y[b, n] = sum_kk X[b, kk] * Bop(n, kk) + bias[n]
//   Bop(n=8i+c, kk) = W[i*32768 + kk*8 + c]
// M=512, N=4096, K=4096.
// R5: 512 threads / 16 warps (4x4), warp tile 32x32 -> 4 warps per SMSP for
// latency hiding; per-warp ILP chains shorter, regs ~85.

#define M_DIM 512
#define N_DIM 4096
#define K_DIM 4096
#define BM 128
#define BN 128
#define BK 32
#define NK (K_DIM / BK)         // 128
#define STAGES 3
#define THREADS 512

#define A_STRIDE 36                       // padded floats per A row (conflict-free)
#define A_STAGE_FLT (BM * A_STRIDE)       // 4608
#define B_STAGE_FLT ((BN / 8) * BK * 8)   // 4096  ([16 oct][32 k][8 c])
#define SMEM_BYTES ((STAGES * (A_STAGE_FLT + B_STAGE_FLT)) * 4)  // 104448

__device__ __forceinline__ uint32_t smem_u32(const void* p) {
    uint32_t a;
    asm("{ .reg .u64 t; cvta.to.shared.u64 t, %1; cvt.u32.u64 %0, t; }" : "=r"(a) : "l"(p));
    return a;
}
__device__ __forceinline__ uint32_t f2tf(float f) {
    uint32_t r;
    asm("cvt.rna.tf32.f32 %0, %1;" : "=r"(r) : "f"(f));
    return r;
}
__device__ __forceinline__ void cp16(uint32_t dst, const void* src) {
    asm volatile("cp.async.cg.shared.global [%0], [%1], 16;" :: "r"(dst), "l"(src));
}
#define CP_COMMIT() asm volatile("cp.async.commit_group;" ::: "memory")
#define CP_WAIT(n)  asm volatile("cp.async.wait_group %0;" :: "n"(n) : "memory")

__device__ __forceinline__ void mma8(float* c, const uint32_t* a, const uint32_t* b) {
    asm volatile(
        "mma.sync.aligned.m16n8k8.row.col.f32.tf32.tf32.f32 "
        "{%0,%1,%2,%3}, {%4,%5,%6,%7}, {%8,%9}, {%0,%1,%2,%3};"
        : "+f"(c[0]), "+f"(c[1]), "+f"(c[2]), "+f"(c[3])
        : "r"(a[0]), "r"(a[1]), "r"(a[2]), "r"(a[3]), "r"(b[0]), "r"(b[1]));
}

__global__ __launch_bounds__(THREADS, 1)
void oct_mma_tf32(const float* __restrict__ X,
                  const float* __restrict__ W,
                  const float* __restrict__ Bias,
                  float* __restrict__ Y)
{
    extern __shared__ float smem[];
    float* As = smem;                            // [STAGES][128][36]
    float* Bs = smem + STAGES * A_STAGE_FLT;     // [STAGES][16][32][8]
    const uint32_t sA = smem_u32(As);
    const uint32_t sB = smem_u32(Bs);

    const int t = threadIdx.x;
    const int w = t >> 5;               // 0..15
    const int l = t & 31;
    const int bm = blockIdx.y * BM;
    const int bn = blockIdx.x * BN;
    const int wm = (w & 3) * 32;        // warp M base within tile
    const int wn = (w >> 2) * 32;       // warp N base within tile

    const int lr = l >> 2;              // 0..7
    const int lc = l & 3;               // 0..3

    // ---- cp.async mappings (per thread: 2 A chunks + 2 B chunks of 16 B) ----
    const int i0 = bn >> 3;

    auto issue_stage = [&](int kt, int s) {
        const uint32_t aBase = sA + (uint32_t)s * (A_STAGE_FLT * 4);
        const uint32_t bBase = sB + (uint32_t)s * (B_STAGE_FLT * 4);
        #pragma unroll
        for (int r = 0; r < 2; r++) {
            const int id = t + r * THREADS;
            const int row = id >> 3, c16 = id & 7;
            cp16(aBase + (uint32_t)row * (A_STRIDE * 4) + (uint32_t)c16 * 16,
                 X + (size_t)(bm + row) * K_DIM + (size_t)kt * BK + c16 * 4);
        }
        #pragma unroll
        for (int r = 0; r < 2; r++) {
            const int id = t + r * THREADS;
            const int oct = id >> 6, inner = id & 63;
            cp16(bBase + (uint32_t)oct * 1024 + (uint32_t)inner * 16,
                 W + (size_t)(i0 + oct) * 32768 + (size_t)kt * 256 + inner * 4);
        }
    };

    // ---- prologue: prefetch STAGES-1 stages ----
    #pragma unroll
    for (int s = 0; s < STAGES - 1; s++) {
        issue_stage(s, s);
        CP_COMMIT();
    }

    float acc[2][4][4];
    #pragma unroll
    for (int mi = 0; mi < 2; mi++)
        #pragma unroll
        for (int j = 0; j < 4; j++)
            #pragma unroll
            for (int q = 0; q < 4; q++) acc[mi][j][q] = 0.0f;

    for (int kt = 0; kt < NK; kt++) {
        const int s = kt % STAGES;
        CP_WAIT(STAGES - 2);
        __syncthreads();

        // prefetch stage kt+STAGES-1 into the slot freed last iteration
        {
            const int pf = kt + STAGES - 1;
            if (pf < NK) issue_stage(pf, pf % STAGES);
            CP_COMMIT();
        }

        const float* a = As + s * A_STAGE_FLT;
        const float* b = Bs + s * B_STAGE_FLT;

        #pragma unroll
        for (int ks = 0; ks < 4; ks++) {
            const int k0 = ks * 8;
            uint32_t af[2][4], bf[4][2];
            #pragma unroll
            for (int mi = 0; mi < 2; mi++) {
                const int row = wm + mi * 16 + lr;
                af[mi][0] = f2tf(a[row * A_STRIDE + k0 + lc]);
                af[mi][1] = f2tf(a[(row + 8) * A_STRIDE + k0 + lc]);
                af[mi][2] = f2tf(a[row * A_STRIDE + k0 + 4 + lc]);
                af[mi][3] = f2tf(a[(row + 8) * A_STRIDE + k0 + 4 + lc]);
            }
            #pragma unroll
            for (int j = 0; j < 4; j++) {
                const int oct = (wn >> 3) + j;
                bf[j][0] = f2tf(b[oct * 256 + (k0 + lc) * 8 + lr]);
                bf[j][1] = f2tf(b[oct * 256 + (k0 + 4 + lc) * 8 + lr]);
            }
            #pragma unroll
            for (int mi = 0; mi < 2; mi++)
                #pragma unroll
                for (int j = 0; j < 4; j++)
                    mma8(acc[mi][j], af[mi], bf[j]);
        }
    }

    // ---- epilogue: bias add + store (c-frag: rows lr, lr+8; cols 2*lc, 2*lc+1) ----
    const int r0 = bm + wm + lr;
    #pragma unroll
    for (int mi = 0; mi < 2; mi++) {
        #pragma unroll
        for (int j = 0; j < 4; j++) {
            const int n0 = bn + wn + j * 8 + lc * 2;
            const float b0v = Bias[n0];
            const float b1v = Bias[n0 + 1];
            float2 v0 = make_float2(acc[mi][j][0] + b0v, acc[mi][j][1] + b1v);
            float2 v1 = make_float2(acc[mi][j][2] + b0v, acc[mi][j][3] + b1v);
            *(float2*)(Y + (size_t)(r0 + mi * 16) * N_DIM + n0) = v0;
            *(float2*)(Y + (size_t)(r0 + mi * 16 + 8) * N_DIM + n0) = v1;
        }
    }
}

extern "C" void kernel_launch(void* const* d_in, const int* in_sizes, int n_in,
                              void* d_out, int out_size)
{
    const float* x    = (const float*)d_in[0];  // [512, 4096]
    const float* wt   = (const float*)d_in[1];  // [512, 512, 8, 8]
    const float* bias = (const float*)d_in[2];  // [512, 8]
    float* y          = (float*)d_out;          // [512, 4096]

    cudaFuncSetAttribute(oct_mma_tf32, cudaFuncAttributeMaxDynamicSharedMemorySize, SMEM_BYTES);
    dim3 grid(N_DIM / BN, M_DIM / BM);  // (32, 4) = 128 CTAs
    oct_mma_tf32<<<grid, THREADS, SMEM_BYTES>>>(x, wt, bias, y);
}

// round 7
// speedup vs baseline: 1.6723x; 1.6723x over previous
#include <cuda_runtime.h>
#include <cstdint>

// OctonionLinear as dense tf32 mma.sync GEMM (portable sm_103 target):
//   Y[b, n] = sum_kk X[b, kk] * Bop(n, kk) + bias[n]
//   Bop(n=8i+c, kk) = W[i*32768 + kk*8 + c]
// M=512, N=4096, K=4096.
// R6: R4 shape (256 thr, warp tile 32x64) + split-K(2) -> 256 CTAs, 2 CTAs/SM
// co-resident (regs capped at 128), atomicAdd epilogue onto zeroed Y.

#define M_DIM 512
#define N_DIM 4096
#define K_DIM 4096
#define BM 128
#define BN 128
#define BK 32
#define NK (K_DIM / BK)         // 128
#define KSPLIT 2
#define NK_PER (NK / KSPLIT)    // 64
#define STAGES 3
#define THREADS 256

#define A_STRIDE 36                       // padded floats per A row (conflict-free)
#define A_STAGE_FLT (BM * A_STRIDE)       // 4608
#define B_STAGE_FLT ((BN / 8) * BK * 8)   // 4096  ([16 oct][32 k][8 c])
#define SMEM_BYTES ((STAGES * (A_STAGE_FLT + B_STAGE_FLT)) * 4)  // 104448

__device__ __forceinline__ uint32_t smem_u32(const void* p) {
    uint32_t a;
    asm("{ .reg .u64 t; cvta.to.shared.u64 t, %1; cvt.u32.u64 %0, t; }" : "=r"(a) : "l"(p));
    return a;
}
__device__ __forceinline__ uint32_t f2tf(float f) {
    uint32_t r;
    asm("cvt.rna.tf32.f32 %0, %1;" : "=r"(r) : "f"(f));
    return r;
}
__device__ __forceinline__ void cp16(uint32_t dst, const void* src) {
    asm volatile("cp.async.cg.shared.global [%0], [%1], 16;" :: "r"(dst), "l"(src));
}
#define CP_COMMIT() asm volatile("cp.async.commit_group;" ::: "memory")
#define CP_WAIT(n)  asm volatile("cp.async.wait_group %0;" :: "n"(n) : "memory")

__device__ __forceinline__ void mma8(float* c, const uint32_t* a, const uint32_t* b) {
    asm volatile(
        "mma.sync.aligned.m16n8k8.row.col.f32.tf32.tf32.f32 "
        "{%0,%1,%2,%3}, {%4,%5,%6,%7}, {%8,%9}, {%0,%1,%2,%3};"
        : "+f"(c[0]), "+f"(c[1]), "+f"(c[2]), "+f"(c[3])
        : "r"(a[0]), "r"(a[1]), "r"(a[2]), "r"(a[3]), "r"(b[0]), "r"(b[1]));
}

__global__ __launch_bounds__(THREADS, 2)
void oct_mma_tf32_sk(const float* __restrict__ X,
                     const float* __restrict__ W,
                     const float* __restrict__ Bias,
                     float* __restrict__ Y)
{
    extern __shared__ float smem[];
    float* As = smem;                            // [STAGES][128][36]
    float* Bs = smem + STAGES * A_STAGE_FLT;     // [STAGES][16][32][8]
    const uint32_t sA = smem_u32(As);
    const uint32_t sB = smem_u32(Bs);

    const int t = threadIdx.x;
    const int w = t >> 5;
    const int l = t & 31;
    const int bm = blockIdx.y * BM;
    const int bn = blockIdx.x * BN;
    const int ks0 = blockIdx.z * NK_PER;   // K-tile base for this split
    const int wm = (w & 3) * 32;           // warp M base within tile
    const int wn = (w >> 2) * 64;          // warp N base within tile

    const int lr = l >> 2;                 // 0..7
    const int lc = l & 3;                  // 0..3

    const int i0 = bn >> 3;

    auto issue_stage = [&](int kt, int s) {
        const uint32_t aBase = sA + (uint32_t)s * (A_STAGE_FLT * 4);
        const uint32_t bBase = sB + (uint32_t)s * (B_STAGE_FLT * 4);
        #pragma unroll
        for (int r = 0; r < 4; r++) {
            const int id = t + r * 256;
            const int row = id >> 3, c16 = id & 7;
            cp16(aBase + (uint32_t)row * (A_STRIDE * 4) + (uint32_t)c16 * 16,
                 X + (size_t)(bm + row) * K_DIM + (size_t)kt * BK + c16 * 4);
        }
        #pragma unroll
        for (int r = 0; r < 4; r++) {
            const int id = t + r * 256;
            const int oct = id >> 6, inner = id & 63;
            cp16(bBase + (uint32_t)oct * 1024 + (uint32_t)inner * 16,
                 W + (size_t)(i0 + oct) * 32768 + (size_t)kt * 256 + inner * 4);
        }
    };

    // ---- prologue: prefetch STAGES-1 stages ----
    #pragma unroll
    for (int s = 0; s < STAGES - 1; s++) {
        issue_stage(ks0 + s, s);
        CP_COMMIT();
    }

    // ---- acc init: split 0 carries the bias, split 1 carries zero ----
    float acc[2][8][4];
    if (blockIdx.z == 0) {
        #pragma unroll
        for (int j = 0; j < 8; j++) {
            const int n0 = bn + wn + j * 8 + lc * 2;
            const float b0v = Bias[n0];
            const float b1v = Bias[n0 + 1];
            #pragma unroll
            for (int mi = 0; mi < 2; mi++) {
                acc[mi][j][0] = b0v; acc[mi][j][1] = b1v;
                acc[mi][j][2] = b0v; acc[mi][j][3] = b1v;
            }
        }
    } else {
        #pragma unroll
        for (int mi = 0; mi < 2; mi++)
            #pragma unroll
            for (int j = 0; j < 8; j++)
                #pragma unroll
                for (int q = 0; q < 4; q++) acc[mi][j][q] = 0.0f;
    }

    for (int kt = 0; kt < NK_PER; kt++) {
        const int s = kt % STAGES;
        CP_WAIT(STAGES - 2);
        __syncthreads();

        {
            const int pf = kt + STAGES - 1;
            if (pf < NK_PER) issue_stage(ks0 + pf, pf % STAGES);
            CP_COMMIT();
        }

        const float* a = As + s * A_STAGE_FLT;
        const float* b = Bs + s * B_STAGE_FLT;

        #pragma unroll
        for (int ksi = 0; ksi < 4; ksi++) {
            const int k0 = ksi * 8;
            uint32_t af[2][4], bf[8][2];
            #pragma unroll
            for (int mi = 0; mi < 2; mi++) {
                const int row = wm + mi * 16 + lr;
                af[mi][0] = f2tf(a[row * A_STRIDE + k0 + lc]);
                af[mi][1] = f2tf(a[(row + 8) * A_STRIDE + k0 + lc]);
                af[mi][2] = f2tf(a[row * A_STRIDE + k0 + 4 + lc]);
                af[mi][3] = f2tf(a[(row + 8) * A_STRIDE + k0 + 4 + lc]);
            }
            #pragma unroll
            for (int j = 0; j < 8; j++) {
                const int oct = (wn >> 3) + j;
                bf[j][0] = f2tf(b[oct * 256 + (k0 + lc) * 8 + lr]);
                bf[j][1] = f2tf(b[oct * 256 + (k0 + 4 + lc) * 8 + lr]);
            }
            #pragma unroll
            for (int mi = 0; mi < 2; mi++)
                #pragma unroll
                for (int j = 0; j < 8; j++)
                    mma8(acc[mi][j], af[mi], bf[j]);
        }
    }

    // ---- epilogue: atomicAdd partial sums into zeroed Y ----
    const int r0 = bm + wm + lr;
    #pragma unroll
    for (int mi = 0; mi < 2; mi++) {
        #pragma unroll
        for (int j = 0; j < 8; j++) {
            const int n0 = bn + wn + j * 8 + lc * 2;
            float* y0 = Y + (size_t)(r0 + mi * 16) * N_DIM + n0;
            float* y1 = Y + (size_t)(r0 + mi * 16 + 8) * N_DIM + n0;
            atomicAdd(y0,     acc[mi][j][0]);
            atomicAdd(y0 + 1, acc[mi][j][1]);
            atomicAdd(y1,     acc[mi][j][2]);
            atomicAdd(y1 + 1, acc[mi][j][3]);
        }
    }
}

extern "C" void kernel_launch(void* const* d_in, const int* in_sizes, int n_in,
                              void* d_out, int out_size)
{
    const float* x    = (const float*)d_in[0];  // [512, 4096]
    const float* wt   = (const float*)d_in[1];  // [512, 512, 8, 8]
    const float* bias = (const float*)d_in[2];  // [512, 8]
    float* y          = (float*)d_out;          // [512, 4096]

    cudaMemsetAsync(y, 0, (size_t)M_DIM * N_DIM * sizeof(float));

    cudaFuncSetAttribute(oct_mma_tf32_sk, cudaFuncAttributeMaxDynamicSharedMemorySize, SMEM_BYTES);
    dim3 grid(N_DIM / BN, M_DIM / BM, KSPLIT);  // (32, 4, 2) = 256 CTAs
    oct_mma_tf32_sk<<<grid, THREADS, SMEM_BYTES>>>(x, wt, bias, y);
}